// round 3
// baseline (speedup 1.0000x reference)
#include <cuda_runtime.h>
#include <cuda_bf16.h>
#include <cstdint>

#define S_LEN 2048
#define HID   4096
#define NH    32
#define NKV   8
#define HD    128

// ---------------- scratch (static device globals; no allocation) -------------
__device__ float g_qlin[(size_t)S_LEN * HID];          // [S, 4096]
__device__ float g_klin[(size_t)S_LEN * (NKV * HD)];   // [S, 1024]
__device__ float g_vlin[(size_t)S_LEN * (NKV * HD)];   // [S, 1024]
__device__ float g_q[(size_t)NH * S_LEN * HD];         // [32][S][128]
__device__ float g_k[(size_t)NKV * S_LEN * HD];        // [8][S][128]
__device__ float g_attn[(size_t)S_LEN * HID];          // [S, 4096]

// =============================================================================
// SGEMM NT: C[M,N] = A[M,K] * B[N,K]^T   (A,B row-major, K-major contiguous)
// BM=BN=128, BK=16, 256 threads, 8x8 micro-tile per thread,
// double-buffered smem with register prefetch.
// Assumes M%128==0, N%128==0, K%16==0 (true for all calls here).
// =============================================================================
__global__ __launch_bounds__(256) void sgemm_nt(
    const float* __restrict__ A, const float* __restrict__ B,
    float* __restrict__ C, int M, int N, int K)
{
    __shared__ float As[2][16][128];
    __shared__ float Bs[2][16][128];

    int tid = threadIdx.x;
    int tx = tid & 15;        // 0..15 (N dim)
    int ty = tid >> 4;        // 0..15 (M dim)
    int mbase = blockIdx.y * 128;
    int nbase = blockIdx.x * 128;

    int lrow = tid >> 2;            // 0..63
    int lcol = (tid & 3) * 4;       // 0,4,8,12
    const float* Ag = A + (size_t)(mbase + lrow) * K + lcol;
    const float* Bg = B + (size_t)(nbase + lrow) * K + lcol;
    size_t rowK64 = (size_t)64 * K;

    // preload tile 0
    {
        float4 a0 = *(const float4*)(Ag);
        float4 a1 = *(const float4*)(Ag + rowK64);
        float4 b0 = *(const float4*)(Bg);
        float4 b1 = *(const float4*)(Bg + rowK64);
        As[0][lcol + 0][lrow] = a0.x; As[0][lcol + 1][lrow] = a0.y;
        As[0][lcol + 2][lrow] = a0.z; As[0][lcol + 3][lrow] = a0.w;
        As[0][lcol + 0][lrow + 64] = a1.x; As[0][lcol + 1][lrow + 64] = a1.y;
        As[0][lcol + 2][lrow + 64] = a1.z; As[0][lcol + 3][lrow + 64] = a1.w;
        Bs[0][lcol + 0][lrow] = b0.x; Bs[0][lcol + 1][lrow] = b0.y;
        Bs[0][lcol + 2][lrow] = b0.z; Bs[0][lcol + 3][lrow] = b0.w;
        Bs[0][lcol + 0][lrow + 64] = b1.x; Bs[0][lcol + 1][lrow + 64] = b1.y;
        Bs[0][lcol + 2][lrow + 64] = b1.z; Bs[0][lcol + 3][lrow + 64] = b1.w;
    }
    __syncthreads();

    float acc[8][8];
    #pragma unroll
    for (int i = 0; i < 8; i++)
        #pragma unroll
        for (int j = 0; j < 8; j++) acc[i][j] = 0.f;

    int kt = K >> 4;
    int cur = 0;
    for (int t = 0; t < kt; t++) {
        float4 pa0, pa1, pb0, pb1;
        if (t + 1 < kt) {
            int kb = (t + 1) << 4;
            pa0 = *(const float4*)(Ag + kb);
            pa1 = *(const float4*)(Ag + rowK64 + kb);
            pb0 = *(const float4*)(Bg + kb);
            pb1 = *(const float4*)(Bg + rowK64 + kb);
        }
        #pragma unroll
        for (int k = 0; k < 16; k++) {
            float4 af0 = *(const float4*)&As[cur][k][ty * 4];
            float4 af1 = *(const float4*)&As[cur][k][ty * 4 + 64];
            float4 bf0 = *(const float4*)&Bs[cur][k][tx * 4];
            float4 bf1 = *(const float4*)&Bs[cur][k][tx * 4 + 64];
            float av[8] = {af0.x, af0.y, af0.z, af0.w, af1.x, af1.y, af1.z, af1.w};
            float bv[8] = {bf0.x, bf0.y, bf0.z, bf0.w, bf1.x, bf1.y, bf1.z, bf1.w};
            #pragma unroll
            for (int i = 0; i < 8; i++)
                #pragma unroll
                for (int j = 0; j < 8; j++)
                    acc[i][j] += av[i] * bv[j];
        }
        if (t + 1 < kt) {
            int nb = cur ^ 1;
            As[nb][lcol + 0][lrow] = pa0.x; As[nb][lcol + 1][lrow] = pa0.y;
            As[nb][lcol + 2][lrow] = pa0.z; As[nb][lcol + 3][lrow] = pa0.w;
            As[nb][lcol + 0][lrow + 64] = pa1.x; As[nb][lcol + 1][lrow + 64] = pa1.y;
            As[nb][lcol + 2][lrow + 64] = pa1.z; As[nb][lcol + 3][lrow + 64] = pa1.w;
            Bs[nb][lcol + 0][lrow] = pb0.x; Bs[nb][lcol + 1][lrow] = pb0.y;
            Bs[nb][lcol + 2][lrow] = pb0.z; Bs[nb][lcol + 3][lrow] = pb0.w;
            Bs[nb][lcol + 0][lrow + 64] = pb1.x; Bs[nb][lcol + 1][lrow + 64] = pb1.y;
            Bs[nb][lcol + 2][lrow + 64] = pb1.z; Bs[nb][lcol + 3][lrow + 64] = pb1.w;
            __syncthreads();
            cur = nb;
        }
    }

    #pragma unroll
    for (int ih = 0; ih < 2; ih++) {
        #pragma unroll
        for (int i = 0; i < 4; i++) {
            int r = mbase + ty * 4 + i + ih * 64;
            #pragma unroll
            for (int jh = 0; jh < 2; jh++) {
                float4 o;
                o.x = acc[ih * 4 + i][jh * 4 + 0];
                o.y = acc[ih * 4 + i][jh * 4 + 1];
                o.z = acc[ih * 4 + i][jh * 4 + 2];
                o.w = acc[ih * 4 + i][jh * 4 + 3];
                *(float4*)&C[(size_t)r * N + nbase + tx * 4 + jh * 64] = o;
            }
        }
    }
}

// =============================================================================
// Per-(s, head) RMSNorm + RoPE.  grid=(S, 40): y<32 -> Q head, y>=32 -> K head.
// Writes head-major [h][s][d] layouts for attention.
// =============================================================================
__global__ __launch_bounds__(128) void qk_norm_rope(
    const float* __restrict__ qlin, const float* __restrict__ klin,
    const float* __restrict__ qw, const float* __restrict__ kw,
    const int* __restrict__ pos_ids,
    const float* __restrict__ cosT, const float* __restrict__ sinT,
    float* __restrict__ qout, float* __restrict__ kout)
{
    int s = blockIdx.x;
    int hb = blockIdx.y;
    int i = threadIdx.x;

    float x;
    const float* w;
    float* dst;
    if (hb < NH) {
        x = qlin[(size_t)s * HID + hb * HD + i];
        w = qw;
        dst = qout + ((size_t)hb * S_LEN + s) * HD;
    } else {
        int hk = hb - NH;
        x = klin[(size_t)s * (NKV * HD) + hk * HD + i];
        w = kw;
        dst = kout + ((size_t)hk * S_LEN + s) * HD;
    }

    __shared__ float red[128];
    __shared__ float xs[128];
    __shared__ float s_inv;

    red[i] = x * x;
    __syncthreads();
    if (i < 64) red[i] += red[i + 64];
    __syncthreads();
    if (i < 32) {
        float v = red[i] + red[i + 32];
        #pragma unroll
        for (int o = 16; o > 0; o >>= 1) v += __shfl_xor_sync(0xffffffffu, v, o);
        if (i == 0) s_inv = rsqrtf(v * (1.0f / 128.0f) + 1e-6f);
    }
    __syncthreads();

    float xn = x * s_inv * w[i];
    xs[i] = xn;
    __syncthreads();
    float other = (i < 64) ? -xs[i + 64] : xs[i - 64];
    int p = pos_ids[s];
    float c = cosT[(size_t)p * HD + i];
    float sn = sinT[(size_t)p * HD + i];
    dst[i] = xn * c + other * sn;
}

// =============================================================================
// Flash attention (fp32, causal, GQA 4:1).
// grid=(16 q-blocks, 32 heads), 256 threads.  BM=128, BN=64, d=128.
// Q: [32][S][128], K: [8][S][128], V: [S][1024] (s-major), Out: [S][4096].
// =============================================================================
#define ATT_SMEM_FLOATS (128 * 132 + 64 * 132 + 64 * 128 + 128 * 68)
#define ATT_SMEM_BYTES  (ATT_SMEM_FLOATS * 4)

__global__ __launch_bounds__(256) void attn_kernel(
    const float* __restrict__ Q, const float* __restrict__ Kc,
    const float* __restrict__ V, float* __restrict__ Out)
{
    extern __shared__ float sm[];
    float* Qs = sm;                    // [128][132]
    float* Ks = Qs + 128 * 132;        // [64][132]
    float* Vs = Ks + 64 * 132;         // [64][128]
    float* Ps = Vs + 64 * 128;         // [128][68]

    int h = blockIdx.y;
    int qb = blockIdx.x;
    int kvh = h >> 2;
    int qbase = qb * 128;
    int tid = threadIdx.x;
    int tx = tid & 7;     // 8 (N / O-col groups)
    int ty = tid >> 3;    // 32 (each owns 4 rows)

    // load Q tile [128][128]
    const float* qsrc = Q + ((size_t)h * S_LEN + qbase) * HD;
    for (int idx = tid; idx < 128 * 32; idx += 256) {
        int r = idx >> 5, c = (idx & 31) * 4;
        float4 v4 = *(const float4*)(qsrc + r * HD + c);
        *(float4*)&Qs[r * 132 + c] = v4;
    }

    float m_i[4], l_i[4], acc[4][16];
    #pragma unroll
    for (int i = 0; i < 4; i++) {
        m_i[i] = -1e30f;
        l_i[i] = 0.f;
        #pragma unroll
        for (int c = 0; c < 16; c++) acc[i][c] = 0.f;
    }

    int nkt = 2 * (qb + 1);
    const float scale = 0.08838834764831845f;  // 1/sqrt(128)

    for (int kt = 0; kt < nkt; kt++) {
        int n0 = kt * 64;
        __syncthreads();  // prior O-gemm done reading Ks/Vs/Ps
        const float* ksrc = Kc + ((size_t)kvh * S_LEN + n0) * HD;
        const float* vsrc = V + (size_t)n0 * (NKV * HD) + kvh * HD;
        for (int idx = tid; idx < 64 * 32; idx += 256) {
            int r = idx >> 5, c = (idx & 31) * 4;
            float4 kv = *(const float4*)(ksrc + r * HD + c);
            *(float4*)&Ks[r * 132 + c] = kv;
            float4 vv = *(const float4*)(vsrc + (size_t)r * (NKV * HD) + c);
            *(float4*)&Vs[r * 128 + c] = vv;
        }
        __syncthreads();

        // S = Q K^T tile: per-thread 4x8
        float sv[4][8];
        #pragma unroll
        for (int i = 0; i < 4; i++)
            #pragma unroll
            for (int j = 0; j < 8; j++) sv[i][j] = 0.f;

        #pragma unroll 2
        for (int k = 0; k < 128; k += 4) {
            float4 a[4], b[8];
            #pragma unroll
            for (int i = 0; i < 4; i++) a[i] = *(const float4*)&Qs[(ty * 4 + i) * 132 + k];
            #pragma unroll
            for (int j = 0; j < 8; j++) b[j] = *(const float4*)&Ks[(tx + j * 8) * 132 + k];
            #pragma unroll
            for (int i = 0; i < 4; i++)
                #pragma unroll
                for (int j = 0; j < 8; j++) {
                    sv[i][j] += a[i].x * b[j].x;
                    sv[i][j] += a[i].y * b[j].y;
                    sv[i][j] += a[i].z * b[j].z;
                    sv[i][j] += a[i].w * b[j].w;
                }
        }

        bool maskt = (n0 + 64 > qbase);

        #pragma unroll
        for (int i = 0; i < 4; i++) {
            int row = qbase + ty * 4 + i;
            #pragma unroll
            for (int j = 0; j < 8; j++) {
                float val = sv[i][j] * scale;
                if (maskt && (n0 + tx + j * 8 > row)) val = -1e30f;
                sv[i][j] = val;
            }
            float mr = sv[i][0];
            #pragma unroll
            for (int j = 1; j < 8; j++) mr = fmaxf(mr, sv[i][j]);
            mr = fmaxf(mr, __shfl_xor_sync(0xffffffffu, mr, 1));
            mr = fmaxf(mr, __shfl_xor_sync(0xffffffffu, mr, 2));
            mr = fmaxf(mr, __shfl_xor_sync(0xffffffffu, mr, 4));
            float mnew = fmaxf(m_i[i], mr);
            float alpha = __expf(m_i[i] - mnew);
            float lsum = 0.f;
            #pragma unroll
            for (int j = 0; j < 8; j++) {
                float p = __expf(sv[i][j] - mnew);
                sv[i][j] = p;
                lsum += p;
            }
            lsum += __shfl_xor_sync(0xffffffffu, lsum, 1);
            lsum += __shfl_xor_sync(0xffffffffu, lsum, 2);
            lsum += __shfl_xor_sync(0xffffffffu, lsum, 4);
            l_i[i] = l_i[i] * alpha + lsum;
            m_i[i] = mnew;
            #pragma unroll
            for (int c = 0; c < 16; c++) acc[i][c] *= alpha;
            #pragma unroll
            for (int j = 0; j < 8; j++) Ps[(ty * 4 + i) * 68 + tx + j * 8] = sv[i][j];
        }
        __syncthreads();

        // O += P V : per-thread 4 rows x 16 cols (cols tx*4 + jj*32 + 0..3)
        #pragma unroll 1
        for (int n = 0; n < 64; n += 4) {
            float4 p4[4];
            #pragma unroll
            for (int i = 0; i < 4; i++) p4[i] = *(const float4*)&Ps[(ty * 4 + i) * 68 + n];
            float pcol[4][4];
            #pragma unroll
            for (int i = 0; i < 4; i++) {
                pcol[i][0] = p4[i].x; pcol[i][1] = p4[i].y;
                pcol[i][2] = p4[i].z; pcol[i][3] = p4[i].w;
            }
            #pragma unroll
            for (int ns = 0; ns < 4; ns++) {
                #pragma unroll
                for (int jj = 0; jj < 4; jj++) {
                    float4 v4 = *(const float4*)&Vs[(n + ns) * 128 + tx * 4 + jj * 32];
                    #pragma unroll
                    for (int i = 0; i < 4; i++) {
                        acc[i][jj * 4 + 0] += pcol[i][ns] * v4.x;
                        acc[i][jj * 4 + 1] += pcol[i][ns] * v4.y;
                        acc[i][jj * 4 + 2] += pcol[i][ns] * v4.z;
                        acc[i][jj * 4 + 3] += pcol[i][ns] * v4.w;
                    }
                }
            }
        }
    }

    // epilogue: Out[row][h*128 + col] = acc / l
    #pragma unroll
    for (int i = 0; i < 4; i++) {
        float inv = 1.0f / l_i[i];
        int row = qbase + ty * 4 + i;
        #pragma unroll
        for (int jj = 0; jj < 4; jj++) {
            float4 o;
            o.x = acc[i][jj * 4 + 0] * inv;
            o.y = acc[i][jj * 4 + 1] * inv;
            o.z = acc[i][jj * 4 + 2] * inv;
            o.w = acc[i][jj * 4 + 3] * inv;
            *(float4*)&Out[(size_t)row * HID + h * HD + tx * 4 + jj * 32] = o;
        }
    }
}

// =============================================================================
extern "C" void kernel_launch(void* const* d_in, const int* in_sizes, int n_in,
                              void* d_out, int out_size)
{
    const float* hidden = (const float*)d_in[0];
    const int* pos      = (const int*)d_in[1];
    const float* Wq     = (const float*)d_in[2];
    const float* Wk     = (const float*)d_in[3];
    const float* Wv     = (const float*)d_in[4];
    const float* Wo     = (const float*)d_in[5];
    const float* qw     = (const float*)d_in[6];
    const float* kw     = (const float*)d_in[7];
    const float* cosT   = (const float*)d_in[8];
    const float* sinT   = (const float*)d_in[9];
    float* out = (float*)d_out;

    float *qlin, *klin, *vlin, *qt, *ktb, *attnb;
    cudaGetSymbolAddress((void**)&qlin, g_qlin);
    cudaGetSymbolAddress((void**)&klin, g_klin);
    cudaGetSymbolAddress((void**)&vlin, g_vlin);
    cudaGetSymbolAddress((void**)&qt, g_q);
    cudaGetSymbolAddress((void**)&ktb, g_k);
    cudaGetSymbolAddress((void**)&attnb, g_attn);

    cudaFuncSetAttribute(attn_kernel, cudaFuncAttributeMaxDynamicSharedMemorySize,
                         ATT_SMEM_BYTES);

    // projections
    sgemm_nt<<<dim3(HID / 128, S_LEN / 128), 256>>>(hidden, Wq, qlin, S_LEN, HID, HID);
    sgemm_nt<<<dim3((NKV * HD) / 128, S_LEN / 128), 256>>>(hidden, Wk, klin, S_LEN, NKV * HD, HID);
    sgemm_nt<<<dim3((NKV * HD) / 128, S_LEN / 128), 256>>>(hidden, Wv, vlin, S_LEN, NKV * HD, HID);

    // per-head RMSNorm + RoPE (Q: 32 heads, K: 8 heads)
    qk_norm_rope<<<dim3(S_LEN, NH + NKV), 128>>>(qlin, klin, qw, kw, pos, cosT, sinT, qt, ktb);

    // causal GQA flash attention
    attn_kernel<<<dim3(S_LEN / 128, NH), 256, ATT_SMEM_BYTES>>>(qt, ktb, vlin, attnb);

    // output projection -> d_out
    sgemm_nt<<<dim3(HID / 128, S_LEN / 128), 256>>>(attnb, Wo, out, S_LEN, HID, HID);
}

// round 6
// speedup vs baseline: 1.8238x; 1.8238x over previous
#include <cuda_runtime.h>
#include <cuda_bf16.h>
#include <cstdint>

typedef __nv_bfloat16 bf16;

#define S_LEN 2048
#define HID   4096
#define NH    32
#define NKV   8
#define HD    128

// ---------------- scratch (static device globals; no allocation) -------------
__device__ __align__(256) float g_qlin[(size_t)S_LEN * HID];
__device__ __align__(256) float g_klin[(size_t)S_LEN * (NKV * HD)];
__device__ __align__(256) float g_vlin[(size_t)S_LEN * (NKV * HD)];
__device__ __align__(256) float g_q[(size_t)NH * S_LEN * HD];
__device__ __align__(256) float g_k[(size_t)NKV * S_LEN * HD];
__device__ __align__(256) float g_attn[(size_t)S_LEN * HID];

// split-bf16 copies
__device__ __align__(256) bf16 g_hid_hi[(size_t)S_LEN * HID];
__device__ __align__(256) bf16 g_hid_lo[(size_t)S_LEN * HID];
__device__ __align__(256) bf16 g_wq_hi[(size_t)HID * HID];
__device__ __align__(256) bf16 g_wq_lo[(size_t)HID * HID];
__device__ __align__(256) bf16 g_wk_hi[(size_t)(NKV * HD) * HID];
__device__ __align__(256) bf16 g_wk_lo[(size_t)(NKV * HD) * HID];
__device__ __align__(256) bf16 g_wv_hi[(size_t)(NKV * HD) * HID];
__device__ __align__(256) bf16 g_wv_lo[(size_t)(NKV * HD) * HID];
__device__ __align__(256) bf16 g_wo_hi[(size_t)HID * HID];
__device__ __align__(256) bf16 g_wo_lo[(size_t)HID * HID];
__device__ __align__(256) bf16 g_attn_hi[(size_t)S_LEN * HID];
__device__ __align__(256) bf16 g_attn_lo[(size_t)S_LEN * HID];

// ============================= helpers ======================================
__device__ __forceinline__ uint32_t smem_u32(const void* p) {
    uint32_t a;
    asm("{ .reg .u64 t; cvta.to.shared.u64 t, %1; cvt.u32.u64 %0, t; }"
        : "=r"(a) : "l"(p));
    return a;
}

#define SW128(o) ((o) ^ (((o) >> 3) & 0x70))

__device__ __forceinline__ void cpasync16(uint32_t dst, const void* src) {
    asm volatile("cp.async.cg.shared.global [%0], [%1], 16;"
                 :: "r"(dst), "l"(src));
}

#define LDSM4(r0, r1, r2, r3, a)                                              \
    asm volatile("ldmatrix.sync.aligned.m8n8.x4.shared.b16 {%0,%1,%2,%3}, [%4];" \
        : "=r"(r0), "=r"(r1), "=r"(r2), "=r"(r3) : "r"(a))

#define MMA16816(d, a0, a1, a2, a3, b0, b1)                                   \
    asm volatile("mma.sync.aligned.m16n8k16.row.col.f32.bf16.bf16.f32 "       \
        "{%0,%1,%2,%3}, {%4,%5,%6,%7}, {%8,%9}, {%0,%1,%2,%3};"               \
        : "+f"((d)[0]), "+f"((d)[1]), "+f"((d)[2]), "+f"((d)[3])              \
        : "r"(a0), "r"(a1), "r"(a2), "r"(a3), "r"(b0), "r"(b1))

// ============================================================================
// fp32 -> (bf16 hi, bf16 lo) split conversion, vectorized x4
// ============================================================================
__global__ __launch_bounds__(256) void cvt_hilo(
    const float4* __restrict__ x, __nv_bfloat162* __restrict__ hi,
    __nv_bfloat162* __restrict__ lo, int n4)
{
    int i = blockIdx.x * 256 + threadIdx.x;
    if (i >= n4) return;
    float4 v = x[i];
    bf16 h0 = __float2bfloat16(v.x), h1 = __float2bfloat16(v.y);
    bf16 h2 = __float2bfloat16(v.z), h3 = __float2bfloat16(v.w);
    bf16 l0 = __float2bfloat16(v.x - __bfloat162float(h0));
    bf16 l1 = __float2bfloat16(v.y - __bfloat162float(h1));
    bf16 l2 = __float2bfloat16(v.z - __bfloat162float(h2));
    bf16 l3 = __float2bfloat16(v.w - __bfloat162float(h3));
    hi[2 * i]     = __halves2bfloat162(h0, h1);
    hi[2 * i + 1] = __halves2bfloat162(h2, h3);
    lo[2 * i]     = __halves2bfloat162(l0, l1);
    lo[2 * i + 1] = __halves2bfloat162(l2, l3);
}

// ============================================================================
// HMMA split-bf16 GEMM: C[M,N] = A[M,K]*B[N,K]^T, fp32-accurate via 3 terms.
// CTA 128x128, BK=64, 8 warps (2x4), warp tile 64x32, SW128 smem,
// 2-stage cp.async double buffer.  Requires M%128==0, N%128==0, K%64==0.
// ============================================================================
#define GS_A  16384u                 // one 128x64 bf16 tile (128B rows) = 16KB
#define GSTG  65536u                 // stage = Ah,Al,Bh,Bl
#define GEMM_SMEM_BYTES (2 * 65536)

__global__ __launch_bounds__(256) void hmma_gemm(
    const bf16* __restrict__ Ah, const bf16* __restrict__ Al,
    const bf16* __restrict__ Bh, const bf16* __restrict__ Bl,
    float* __restrict__ C, int M, int N, int K)
{
    extern __shared__ char smc[];
    uint32_t sb = smem_u32(smc);

    int tid = threadIdx.x;
    int wid = tid >> 5, lane = tid & 31;
    int mbase = blockIdx.y * 128, nbase = blockIdx.x * 128;
    int warpM = (wid & 1) * 64;
    int warpN = (wid >> 1) * 32;

    const bf16* Aho = Ah + (size_t)mbase * K;
    const bf16* Alo = Al + (size_t)mbase * K;
    const bf16* Bho = Bh + (size_t)nbase * K;
    const bf16* Blo = Bl + (size_t)nbase * K;

    const int KT = K >> 6;

    // per-stage loader: 4 tiles of 128 rows x 64 bf16 (128B rows), SW128
    auto load_stage = [&](int s, int kt) {
        uint32_t sa = sb + (uint32_t)s * GSTG;
        int kb = kt << 6;
        #pragma unroll
        for (int i = 0; i < 4; i++) {
            int idx = tid + i * 256;          // 0..1023
            int row = idx >> 3;
            int c8 = idx & 7;
            uint32_t off = SW128((uint32_t)(row * 128 + c8 * 16));
            size_t g = (size_t)row * K + kb + c8 * 8;
            cpasync16(sa + off,              Aho + g);
            cpasync16(sa + GS_A + off,       Alo + g);
            cpasync16(sa + 2 * GS_A + off,   Bho + g);
            cpasync16(sa + 3 * GS_A + off,   Blo + g);
        }
        asm volatile("cp.async.commit_group;" ::: "memory");
    };

    float acc[4][4][4];
    #pragma unroll
    for (int a = 0; a < 4; a++)
        #pragma unroll
        for (int b = 0; b < 4; b++)
            #pragma unroll
            for (int c = 0; c < 4; c++) acc[a][b][c] = 0.f;

    load_stage(0, 0);

    uint32_t lrow = lane & 15;
    uint32_t lcsel = (lane >> 4) * 16;

    for (int kt = 0; kt < KT; kt++) {
        if (kt + 1 < KT) {
            load_stage((kt + 1) & 1, kt + 1);
            asm volatile("cp.async.wait_group 1;" ::: "memory");
        } else {
            asm volatile("cp.async.wait_group 0;" ::: "memory");
        }
        __syncthreads();

        uint32_t st = sb + (uint32_t)(kt & 1) * GSTG;
        #pragma unroll
        for (int kk = 0; kk < 4; kk++) {
            uint32_t acol = kk * 32 + lcsel;
            uint32_t ah4[4][4], al4[4][4];
            #pragma unroll
            for (int mi = 0; mi < 4; mi++) {
                uint32_t off = SW128((uint32_t)((warpM + mi * 16 + lrow) * 128) + acol);
                LDSM4(ah4[mi][0], ah4[mi][1], ah4[mi][2], ah4[mi][3], st + off);
                LDSM4(al4[mi][0], al4[mi][1], al4[mi][2], al4[mi][3], st + GS_A + off);
            }
            uint32_t bh4[2][4], bl4[2][4];
            #pragma unroll
            for (int p = 0; p < 2; p++) {
                uint32_t off = SW128((uint32_t)((warpN + p * 16 + lrow) * 128) + acol);
                LDSM4(bh4[p][0], bh4[p][1], bh4[p][2], bh4[p][3], st + 2 * GS_A + off);
                LDSM4(bl4[p][0], bl4[p][1], bl4[p][2], bl4[p][3], st + 3 * GS_A + off);
            }
            #pragma unroll
            for (int mi = 0; mi < 4; mi++) {
                #pragma unroll
                for (int t = 0; t < 4; t++) {
                    int p = t >> 1, h = t & 1;
                    MMA16816(acc[mi][t], ah4[mi][0], ah4[mi][1], ah4[mi][2], ah4[mi][3],
                             bh4[p][h], bh4[p][h + 2]);
                    MMA16816(acc[mi][t], ah4[mi][0], ah4[mi][1], ah4[mi][2], ah4[mi][3],
                             bl4[p][h], bl4[p][h + 2]);
                    MMA16816(acc[mi][t], al4[mi][0], al4[mi][1], al4[mi][2], al4[mi][3],
                             bh4[p][h], bh4[p][h + 2]);
                }
            }
        }
        __syncthreads();
    }

    // epilogue
    #pragma unroll
    for (int mi = 0; mi < 4; mi++) {
        int row0 = mbase + warpM + mi * 16 + (lane >> 2);
        #pragma unroll
        for (int t = 0; t < 4; t++) {
            int col = nbase + warpN + t * 8 + (lane & 3) * 2;
            float2 v0 = { acc[mi][t][0], acc[mi][t][1] };
            float2 v1 = { acc[mi][t][2], acc[mi][t][3] };
            *(float2*)&C[(size_t)row0 * N + col] = v0;
            *(float2*)&C[(size_t)(row0 + 8) * N + col] = v1;
        }
    }
}

// =============================================================================
// Per-(s, head) RMSNorm + RoPE
// =============================================================================
__global__ __launch_bounds__(128) void qk_norm_rope(
    const float* __restrict__ qlin, const float* __restrict__ klin,
    const float* __restrict__ qw, const float* __restrict__ kw,
    const int* __restrict__ pos_ids,
    const float* __restrict__ cosT, const float* __restrict__ sinT,
    float* __restrict__ qout, float* __restrict__ kout)
{
    int s = blockIdx.x;
    int hb = blockIdx.y;
    int i = threadIdx.x;

    float x;
    const float* w;
    float* dst;
    if (hb < NH) {
        x = qlin[(size_t)s * HID + hb * HD + i];
        w = qw;
        dst = qout + ((size_t)hb * S_LEN + s) * HD;
    } else {
        int hk = hb - NH;
        x = klin[(size_t)s * (NKV * HD) + hk * HD + i];
        w = kw;
        dst = kout + ((size_t)hk * S_LEN + s) * HD;
    }

    __shared__ float red[128];
    __shared__ float xs[128];
    __shared__ float s_inv;

    red[i] = x * x;
    __syncthreads();
    if (i < 64) red[i] += red[i + 64];
    __syncthreads();
    if (i < 32) {
        float v = red[i] + red[i + 32];
        #pragma unroll
        for (int o = 16; o > 0; o >>= 1) v += __shfl_xor_sync(0xffffffffu, v, o);
        if (i == 0) s_inv = rsqrtf(v * (1.0f / 128.0f) + 1e-6f);
    }
    __syncthreads();

    float xn = x * s_inv * w[i];
    xs[i] = xn;
    __syncthreads();
    float other = (i < 64) ? -xs[i + 64] : xs[i - 64];
    int p = pos_ids[s];
    float c = cosT[(size_t)p * HD + i];
    float sn = sinT[(size_t)p * HD + i];
    dst[i] = xn * c + other * sn;
}

// =============================================================================
// Flash attention (fp32, causal, GQA 4:1)
// =============================================================================
#define ATT_SMEM_FLOATS (128 * 132 + 64 * 132 + 64 * 128 + 128 * 68)
#define ATT_SMEM_BYTES  (ATT_SMEM_FLOATS * 4)

__global__ __launch_bounds__(256) void attn_kernel(
    const float* __restrict__ Q, const float* __restrict__ Kc,
    const float* __restrict__ V, float* __restrict__ Out)
{
    extern __shared__ float sm[];
    float* Qs = sm;                    // [128][132]
    float* Ks = Qs + 128 * 132;        // [64][132]
    float* Vs = Ks + 64 * 132;         // [64][128]
    float* Ps = Vs + 64 * 128;         // [128][68]

    int h = blockIdx.y;
    int qb = blockIdx.x;
    int kvh = h >> 2;
    int qbase = qb * 128;
    int tid = threadIdx.x;
    int tx = tid & 7;
    int ty = tid >> 3;

    const float* qsrc = Q + ((size_t)h * S_LEN + qbase) * HD;
    for (int idx = tid; idx < 128 * 32; idx += 256) {
        int r = idx >> 5, c = (idx & 31) * 4;
        float4 v4 = *(const float4*)(qsrc + r * HD + c);
        *(float4*)&Qs[r * 132 + c] = v4;
    }

    float m_i[4], l_i[4], acc[4][16];
    #pragma unroll
    for (int i = 0; i < 4; i++) {
        m_i[i] = -1e30f;
        l_i[i] = 0.f;
        #pragma unroll
        for (int c = 0; c < 16; c++) acc[i][c] = 0.f;
    }

    int nkt = 2 * (qb + 1);
    const float scale = 0.08838834764831845f;

    for (int kt = 0; kt < nkt; kt++) {
        int n0 = kt * 64;
        __syncthreads();
        const float* ksrc = Kc + ((size_t)kvh * S_LEN + n0) * HD;
        const float* vsrc = V + (size_t)n0 * (NKV * HD) + kvh * HD;
        for (int idx = tid; idx < 64 * 32; idx += 256) {
            int r = idx >> 5, c = (idx & 31) * 4;
            float4 kv = *(const float4*)(ksrc + r * HD + c);
            *(float4*)&Ks[r * 132 + c] = kv;
            float4 vv = *(const float4*)(vsrc + (size_t)r * (NKV * HD) + c);
            *(float4*)&Vs[r * 128 + c] = vv;
        }
        __syncthreads();

        float sv[4][8];
        #pragma unroll
        for (int i = 0; i < 4; i++)
            #pragma unroll
            for (int j = 0; j < 8; j++) sv[i][j] = 0.f;

        #pragma unroll 2
        for (int k = 0; k < 128; k += 4) {
            float4 a[4], b[8];
            #pragma unroll
            for (int i = 0; i < 4; i++) a[i] = *(const float4*)&Qs[(ty * 4 + i) * 132 + k];
            #pragma unroll
            for (int j = 0; j < 8; j++) b[j] = *(const float4*)&Ks[(tx + j * 8) * 132 + k];
            #pragma unroll
            for (int i = 0; i < 4; i++)
                #pragma unroll
                for (int j = 0; j < 8; j++) {
                    sv[i][j] += a[i].x * b[j].x;
                    sv[i][j] += a[i].y * b[j].y;
                    sv[i][j] += a[i].z * b[j].z;
                    sv[i][j] += a[i].w * b[j].w;
                }
        }

        bool maskt = (n0 + 64 > qbase);

        #pragma unroll
        for (int i = 0; i < 4; i++) {
            int row = qbase + ty * 4 + i;
            #pragma unroll
            for (int j = 0; j < 8; j++) {
                float val = sv[i][j] * scale;
                if (maskt && (n0 + tx + j * 8 > row)) val = -1e30f;
                sv[i][j] = val;
            }
            float mr = sv[i][0];
            #pragma unroll
            for (int j = 1; j < 8; j++) mr = fmaxf(mr, sv[i][j]);
            mr = fmaxf(mr, __shfl_xor_sync(0xffffffffu, mr, 1));
            mr = fmaxf(mr, __shfl_xor_sync(0xffffffffu, mr, 2));
            mr = fmaxf(mr, __shfl_xor_sync(0xffffffffu, mr, 4));
            float mnew = fmaxf(m_i[i], mr);
            float alpha = __expf(m_i[i] - mnew);
            float lsum = 0.f;
            #pragma unroll
            for (int j = 0; j < 8; j++) {
                float p = __expf(sv[i][j] - mnew);
                sv[i][j] = p;
                lsum += p;
            }
            lsum += __shfl_xor_sync(0xffffffffu, lsum, 1);
            lsum += __shfl_xor_sync(0xffffffffu, lsum, 2);
            lsum += __shfl_xor_sync(0xffffffffu, lsum, 4);
            l_i[i] = l_i[i] * alpha + lsum;
            m_i[i] = mnew;
            #pragma unroll
            for (int c = 0; c < 16; c++) acc[i][c] *= alpha;
            #pragma unroll
            for (int j = 0; j < 8; j++) Ps[(ty * 4 + i) * 68 + tx + j * 8] = sv[i][j];
        }
        __syncthreads();

        #pragma unroll 1
        for (int n = 0; n < 64; n += 4) {
            float4 p4[4];
            #pragma unroll
            for (int i = 0; i < 4; i++) p4[i] = *(const float4*)&Ps[(ty * 4 + i) * 68 + n];
            float pcol[4][4];
            #pragma unroll
            for (int i = 0; i < 4; i++) {
                pcol[i][0] = p4[i].x; pcol[i][1] = p4[i].y;
                pcol[i][2] = p4[i].z; pcol[i][3] = p4[i].w;
            }
            #pragma unroll
            for (int ns = 0; ns < 4; ns++) {
                #pragma unroll
                for (int jj = 0; jj < 4; jj++) {
                    float4 v4 = *(const float4*)&Vs[(n + ns) * 128 + tx * 4 + jj * 32];
                    #pragma unroll
                    for (int i = 0; i < 4; i++) {
                        acc[i][jj * 4 + 0] += pcol[i][ns] * v4.x;
                        acc[i][jj * 4 + 1] += pcol[i][ns] * v4.y;
                        acc[i][jj * 4 + 2] += pcol[i][ns] * v4.z;
                        acc[i][jj * 4 + 3] += pcol[i][ns] * v4.w;
                    }
                }
            }
        }
    }

    #pragma unroll
    for (int i = 0; i < 4; i++) {
        float inv = 1.0f / l_i[i];
        int row = qbase + ty * 4 + i;
        #pragma unroll
        for (int jj = 0; jj < 4; jj++) {
            float4 o;
            o.x = acc[i][jj * 4 + 0] * inv;
            o.y = acc[i][jj * 4 + 1] * inv;
            o.z = acc[i][jj * 4 + 2] * inv;
            o.w = acc[i][jj * 4 + 3] * inv;
            *(float4*)&Out[(size_t)row * HID + h * HD + tx * 4 + jj * 32] = o;
        }
    }
}

// =============================================================================
extern "C" void kernel_launch(void* const* d_in, const int* in_sizes, int n_in,
                              void* d_out, int out_size)
{
    const float* hidden = (const float*)d_in[0];
    const int* pos      = (const int*)d_in[1];
    const float* Wq     = (const float*)d_in[2];
    const float* Wk     = (const float*)d_in[3];
    const float* Wv     = (const float*)d_in[4];
    const float* Wo     = (const float*)d_in[5];
    const float* qw     = (const float*)d_in[6];
    const float* kw     = (const float*)d_in[7];
    const float* cosT   = (const float*)d_in[8];
    const float* sinT   = (const float*)d_in[9];
    float* out = (float*)d_out;

    float *qlin, *klin, *vlin, *qt, *ktb, *attnb;
    cudaGetSymbolAddress((void**)&qlin, g_qlin);
    cudaGetSymbolAddress((void**)&klin, g_klin);
    cudaGetSymbolAddress((void**)&vlin, g_vlin);
    cudaGetSymbolAddress((void**)&qt, g_q);
    cudaGetSymbolAddress((void**)&ktb, g_k);
    cudaGetSymbolAddress((void**)&attnb, g_attn);

    bf16 *hid_hi, *hid_lo, *wq_hi, *wq_lo, *wk_hi, *wk_lo, *wv_hi, *wv_lo;
    bf16 *wo_hi, *wo_lo, *at_hi, *at_lo;
    cudaGetSymbolAddress((void**)&hid_hi, g_hid_hi);
    cudaGetSymbolAddress((void**)&hid_lo, g_hid_lo);
    cudaGetSymbolAddress((void**)&wq_hi, g_wq_hi);
    cudaGetSymbolAddress((void**)&wq_lo, g_wq_lo);
    cudaGetSymbolAddress((void**)&wk_hi, g_wk_hi);
    cudaGetSymbolAddress((void**)&wk_lo, g_wk_lo);
    cudaGetSymbolAddress((void**)&wv_hi, g_wv_hi);
    cudaGetSymbolAddress((void**)&wv_lo, g_wv_lo);
    cudaGetSymbolAddress((void**)&wo_hi, g_wo_hi);
    cudaGetSymbolAddress((void**)&wo_lo, g_wo_lo);
    cudaGetSymbolAddress((void**)&at_hi, g_attn_hi);
    cudaGetSymbolAddress((void**)&at_lo, g_attn_lo);

    cudaFuncSetAttribute(attn_kernel, cudaFuncAttributeMaxDynamicSharedMemorySize,
                         ATT_SMEM_BYTES);
    cudaFuncSetAttribute(hmma_gemm, cudaFuncAttributeMaxDynamicSharedMemorySize,
                         GEMM_SMEM_BYTES);

    // split conversions
    {
        int n4;
        n4 = S_LEN * HID / 4;
        cvt_hilo<<<(n4 + 255) / 256, 256>>>((const float4*)hidden,
            (__nv_bfloat162*)hid_hi, (__nv_bfloat162*)hid_lo, n4);
        n4 = HID * HID / 4;
        cvt_hilo<<<(n4 + 255) / 256, 256>>>((const float4*)Wq,
            (__nv_bfloat162*)wq_hi, (__nv_bfloat162*)wq_lo, n4);
        n4 = (NKV * HD) * HID / 4;
        cvt_hilo<<<(n4 + 255) / 256, 256>>>((const float4*)Wk,
            (__nv_bfloat162*)wk_hi, (__nv_bfloat162*)wk_lo, n4);
        cvt_hilo<<<(n4 + 255) / 256, 256>>>((const float4*)Wv,
            (__nv_bfloat162*)wv_hi, (__nv_bfloat162*)wv_lo, n4);
        n4 = HID * HID / 4;
        cvt_hilo<<<(n4 + 255) / 256, 256>>>((const float4*)Wo,
            (__nv_bfloat162*)wo_hi, (__nv_bfloat162*)wo_lo, n4);
    }

    // projections on HMMA tensor cores
    hmma_gemm<<<dim3(HID / 128, S_LEN / 128), 256, GEMM_SMEM_BYTES>>>(
        hid_hi, hid_lo, wq_hi, wq_lo, qlin, S_LEN, HID, HID);
    hmma_gemm<<<dim3((NKV * HD) / 128, S_LEN / 128), 256, GEMM_SMEM_BYTES>>>(
        hid_hi, hid_lo, wk_hi, wk_lo, klin, S_LEN, NKV * HD, HID);
    hmma_gemm<<<dim3((NKV * HD) / 128, S_LEN / 128), 256, GEMM_SMEM_BYTES>>>(
        hid_hi, hid_lo, wv_hi, wv_lo, vlin, S_LEN, NKV * HD, HID);

    // per-head RMSNorm + RoPE
    qk_norm_rope<<<dim3(S_LEN, NH + NKV), 128>>>(qlin, klin, qw, kw, pos, cosT, sinT, qt, ktb);

    // causal GQA flash attention (fp32)
    attn_kernel<<<dim3(S_LEN / 128, NH), 256, ATT_SMEM_BYTES>>>(qt, ktb, vlin, attnb);

    // output projection on HMMA
    {
        int n4 = S_LEN * HID / 4;
        cvt_hilo<<<(n4 + 255) / 256, 256>>>((const float4*)attnb,
            (__nv_bfloat162*)at_hi, (__nv_bfloat162*)at_lo, n4);
    }
    hmma_gemm<<<dim3(HID / 128, S_LEN / 128), 256, GEMM_SMEM_BYTES>>>(
        at_hi, at_lo, wo_hi, wo_lo, out, S_LEN, HID, HID);
}

// round 10
// speedup vs baseline: 2.4459x; 1.3411x over previous
#include <cuda_runtime.h>
#include <cuda_bf16.h>
#include <cstdint>

typedef __nv_bfloat16 bf16;

#define S_LEN 2048
#define HID   4096
#define NH    32
#define NKV   8
#define HD    128

// ---------------- scratch (static device globals; no allocation) -------------
__device__ __align__(256) float g_qlin[(size_t)S_LEN * HID];
__device__ __align__(256) float g_klin[(size_t)S_LEN * (NKV * HD)];
__device__ __align__(256) float g_vlin[(size_t)S_LEN * (NKV * HD)];

// split-bf16 buffers
__device__ __align__(256) bf16 g_hid_hi[(size_t)S_LEN * HID];
__device__ __align__(256) bf16 g_hid_lo[(size_t)S_LEN * HID];
__device__ __align__(256) bf16 g_wq_hi[(size_t)HID * HID];
__device__ __align__(256) bf16 g_wq_lo[(size_t)HID * HID];
__device__ __align__(256) bf16 g_wk_hi[(size_t)(NKV * HD) * HID];
__device__ __align__(256) bf16 g_wk_lo[(size_t)(NKV * HD) * HID];
__device__ __align__(256) bf16 g_wv_hi[(size_t)(NKV * HD) * HID];
__device__ __align__(256) bf16 g_wv_lo[(size_t)(NKV * HD) * HID];
__device__ __align__(256) bf16 g_wo_hi[(size_t)HID * HID];
__device__ __align__(256) bf16 g_wo_lo[(size_t)HID * HID];
__device__ __align__(256) bf16 g_attn_hi[(size_t)S_LEN * HID];
__device__ __align__(256) bf16 g_attn_lo[(size_t)S_LEN * HID];

// attention operands (hi/lo bf16)
__device__ __align__(256) bf16 g_qh[(size_t)NH * S_LEN * HD];
__device__ __align__(256) bf16 g_ql[(size_t)NH * S_LEN * HD];
__device__ __align__(256) bf16 g_kh[(size_t)NKV * S_LEN * HD];
__device__ __align__(256) bf16 g_kl[(size_t)NKV * S_LEN * HD];
__device__ __align__(256) bf16 g_vth[(size_t)NKV * HD * S_LEN];   // [kvh*128+d][s]
__device__ __align__(256) bf16 g_vtl[(size_t)NKV * HD * S_LEN];

// ============================= helpers ======================================
__device__ __forceinline__ uint32_t smem_u32(const void* p) {
    uint32_t a;
    asm("{ .reg .u64 t; cvta.to.shared.u64 t, %1; cvt.u32.u64 %0, t; }"
        : "=r"(a) : "l"(p));
    return a;
}

#define SW128(o) ((o) ^ (((o) >> 3) & 0x70))

__device__ __forceinline__ void cpasync16(uint32_t dst, const void* src) {
    asm volatile("cp.async.cg.shared.global [%0], [%1], 16;"
                 :: "r"(dst), "l"(src));
}

#define LDSM4(r0, r1, r2, r3, a)                                              \
    asm volatile("ldmatrix.sync.aligned.m8n8.x4.shared.b16 {%0,%1,%2,%3}, [%4];" \
        : "=r"(r0), "=r"(r1), "=r"(r2), "=r"(r3) : "r"(a))

#define MMA16816(d, a0, a1, a2, a3, b0, b1)                                   \
    asm volatile("mma.sync.aligned.m16n8k16.row.col.f32.bf16.bf16.f32 "       \
        "{%0,%1,%2,%3}, {%4,%5,%6,%7}, {%8,%9}, {%0,%1,%2,%3};"               \
        : "+f"((d)[0]), "+f"((d)[1]), "+f"((d)[2]), "+f"((d)[3])              \
        : "r"(a0), "r"(a1), "r"(a2), "r"(a3), "r"(b0), "r"(b1))

__device__ __forceinline__ uint32_t pack2(bf16 a, bf16 b) {
    __nv_bfloat162 t = __halves2bfloat162(a, b);
    return *reinterpret_cast<uint32_t*>(&t);
}

__device__ __forceinline__ void psplit(float a, float b, uint32_t& hi, uint32_t& lo) {
    bf16 ha = __float2bfloat16(a), hb = __float2bfloat16(b);
    float ra = a - __bfloat162float(ha), rb = b - __bfloat162float(hb);
    hi = pack2(ha, hb);
    lo = pack2(__float2bfloat16(ra), __float2bfloat16(rb));
}

// ============================================================================
// fp32 -> (bf16 hi, bf16 lo) split conversion, vectorized x4
// ============================================================================
__global__ __launch_bounds__(256) void cvt_hilo(
    const float4* __restrict__ x, __nv_bfloat162* __restrict__ hi,
    __nv_bfloat162* __restrict__ lo, int n4)
{
    int i = blockIdx.x * 256 + threadIdx.x;
    if (i >= n4) return;
    float4 v = x[i];
    bf16 h0 = __float2bfloat16(v.x), h1 = __float2bfloat16(v.y);
    bf16 h2 = __float2bfloat16(v.z), h3 = __float2bfloat16(v.w);
    bf16 l0 = __float2bfloat16(v.x - __bfloat162float(h0));
    bf16 l1 = __float2bfloat16(v.y - __bfloat162float(h1));
    bf16 l2 = __float2bfloat16(v.z - __bfloat162float(h2));
    bf16 l3 = __float2bfloat16(v.w - __bfloat162float(h3));
    hi[2 * i]     = __halves2bfloat162(h0, h1);
    hi[2 * i + 1] = __halves2bfloat162(h2, h3);
    lo[2 * i]     = __halves2bfloat162(l0, l1);
    lo[2 * i + 1] = __halves2bfloat162(l2, l3);
}

// ============================================================================
// V transpose + split: vlin [S][1024] fp32 -> vt_hi/lo [kvh*128+d][S] bf16
// ============================================================================
__global__ __launch_bounds__(256) void vt_cvt(
    const float* __restrict__ v, bf16* __restrict__ th, bf16* __restrict__ tl)
{
    __shared__ float t[32][33];
    int s0 = blockIdx.x * 32, c0 = blockIdx.y * 32;
    int tx = threadIdx.x, ty = threadIdx.y;
    #pragma unroll
    for (int r = 0; r < 4; r++)
        t[ty + r * 8][tx] = v[(size_t)(s0 + ty + r * 8) * (NKV * HD) + c0 + tx];
    __syncthreads();
    #pragma unroll
    for (int r = 0; r < 4; r++) {
        int gc = c0 + ty + r * 8;
        float val = t[tx][ty + r * 8];
        bf16 hh = __float2bfloat16(val);
        bf16 ll = __float2bfloat16(val - __bfloat162float(hh));
        th[(size_t)gc * S_LEN + s0 + tx] = hh;
        tl[(size_t)gc * S_LEN + s0 + tx] = ll;
    }
}

// ============================================================================
// HMMA split-bf16 GEMM (unchanged from R6)
// ============================================================================
#define GS_A  16384u
#define GSTG  65536u
#define GEMM_SMEM_BYTES (2 * 65536)

__global__ __launch_bounds__(256) void hmma_gemm(
    const bf16* __restrict__ Ah, const bf16* __restrict__ Al,
    const bf16* __restrict__ Bh, const bf16* __restrict__ Bl,
    float* __restrict__ C, int M, int N, int K)
{
    extern __shared__ char smc[];
    uint32_t sb = smem_u32(smc);

    int tid = threadIdx.x;
    int wid = tid >> 5, lane = tid & 31;
    int mbase = blockIdx.y * 128, nbase = blockIdx.x * 128;
    int warpM = (wid & 1) * 64;
    int warpN = (wid >> 1) * 32;

    const bf16* Aho = Ah + (size_t)mbase * K;
    const bf16* Alo = Al + (size_t)mbase * K;
    const bf16* Bho = Bh + (size_t)nbase * K;
    const bf16* Blo = Bl + (size_t)nbase * K;

    const int KT = K >> 6;

    auto load_stage = [&](int s, int kt) {
        uint32_t sa = sb + (uint32_t)s * GSTG;
        int kb = kt << 6;
        #pragma unroll
        for (int i = 0; i < 4; i++) {
            int idx = tid + i * 256;
            int row = idx >> 3;
            int c8 = idx & 7;
            uint32_t off = SW128((uint32_t)(row * 128 + c8 * 16));
            size_t g = (size_t)row * K + kb + c8 * 8;
            cpasync16(sa + off,              Aho + g);
            cpasync16(sa + GS_A + off,       Alo + g);
            cpasync16(sa + 2 * GS_A + off,   Bho + g);
            cpasync16(sa + 3 * GS_A + off,   Blo + g);
        }
        asm volatile("cp.async.commit_group;" ::: "memory");
    };

    float acc[4][4][4];
    #pragma unroll
    for (int a = 0; a < 4; a++)
        #pragma unroll
        for (int b = 0; b < 4; b++)
            #pragma unroll
            for (int c = 0; c < 4; c++) acc[a][b][c] = 0.f;

    load_stage(0, 0);

    uint32_t lrow = lane & 15;
    uint32_t lcsel = (lane >> 4) * 16;

    for (int kt = 0; kt < KT; kt++) {
        if (kt + 1 < KT) {
            load_stage((kt + 1) & 1, kt + 1);
            asm volatile("cp.async.wait_group 1;" ::: "memory");
        } else {
            asm volatile("cp.async.wait_group 0;" ::: "memory");
        }
        __syncthreads();

        uint32_t st = sb + (uint32_t)(kt & 1) * GSTG;
        #pragma unroll
        for (int kk = 0; kk < 4; kk++) {
            uint32_t acol = kk * 32 + lcsel;
            uint32_t ah4[4][4], al4[4][4];
            #pragma unroll
            for (int mi = 0; mi < 4; mi++) {
                uint32_t off = SW128((uint32_t)((warpM + mi * 16 + lrow) * 128) + acol);
                LDSM4(ah4[mi][0], ah4[mi][1], ah4[mi][2], ah4[mi][3], st + off);
                LDSM4(al4[mi][0], al4[mi][1], al4[mi][2], al4[mi][3], st + GS_A + off);
            }
            uint32_t bh4[2][4], bl4[2][4];
            #pragma unroll
            for (int p = 0; p < 2; p++) {
                uint32_t off = SW128((uint32_t)((warpN + p * 16 + lrow) * 128) + acol);
                LDSM4(bh4[p][0], bh4[p][1], bh4[p][2], bh4[p][3], st + 2 * GS_A + off);
                LDSM4(bl4[p][0], bl4[p][1], bl4[p][2], bl4[p][3], st + 3 * GS_A + off);
            }
            #pragma unroll
            for (int mi = 0; mi < 4; mi++) {
                #pragma unroll
                for (int t = 0; t < 4; t++) {
                    int p = t >> 1, h = t & 1;
                    MMA16816(acc[mi][t], ah4[mi][0], ah4[mi][1], ah4[mi][2], ah4[mi][3],
                             bh4[p][h], bh4[p][h + 2]);
                    MMA16816(acc[mi][t], ah4[mi][0], ah4[mi][1], ah4[mi][2], ah4[mi][3],
                             bl4[p][h], bl4[p][h + 2]);
                    MMA16816(acc[mi][t], al4[mi][0], al4[mi][1], al4[mi][2], al4[mi][3],
                             bh4[p][h], bh4[p][h + 2]);
                }
            }
        }
        __syncthreads();
    }

    #pragma unroll
    for (int mi = 0; mi < 4; mi++) {
        int row0 = mbase + warpM + mi * 16 + (lane >> 2);
        #pragma unroll
        for (int t = 0; t < 4; t++) {
            int col = nbase + warpN + t * 8 + (lane & 3) * 2;
            float2 v0 = { acc[mi][t][0], acc[mi][t][1] };
            float2 v1 = { acc[mi][t][2], acc[mi][t][3] };
            *(float2*)&C[(size_t)row0 * N + col] = v0;
            *(float2*)&C[(size_t)(row0 + 8) * N + col] = v1;
        }
    }
}

// =============================================================================
// Per-(s, head) RMSNorm + RoPE -> bf16 hi/lo head-major outputs
// =============================================================================
__global__ __launch_bounds__(128) void qk_norm_rope(
    const float* __restrict__ qlin, const float* __restrict__ klin,
    const float* __restrict__ qw, const float* __restrict__ kw,
    const int* __restrict__ pos_ids,
    const float* __restrict__ cosT, const float* __restrict__ sinT,
    bf16* __restrict__ qh, bf16* __restrict__ ql,
    bf16* __restrict__ kh, bf16* __restrict__ kl)
{
    int s = blockIdx.x;
    int hb = blockIdx.y;
    int i = threadIdx.x;

    float x;
    const float* w;
    bf16 *dh, *dl;
    size_t o;
    if (hb < NH) {
        x = qlin[(size_t)s * HID + hb * HD + i];
        w = qw;
        o = ((size_t)hb * S_LEN + s) * HD + i;
        dh = qh; dl = ql;
    } else {
        int hk = hb - NH;
        x = klin[(size_t)s * (NKV * HD) + hk * HD + i];
        w = kw;
        o = ((size_t)hk * S_LEN + s) * HD + i;
        dh = kh; dl = kl;
    }

    __shared__ float red[128];
    __shared__ float xs[128];
    __shared__ float s_inv;

    red[i] = x * x;
    __syncthreads();
    if (i < 64) red[i] += red[i + 64];
    __syncthreads();
    if (i < 32) {
        float v = red[i] + red[i + 32];
        #pragma unroll
        for (int of = 16; of > 0; of >>= 1) v += __shfl_xor_sync(0xffffffffu, v, of);
        if (i == 0) s_inv = rsqrtf(v * (1.0f / 128.0f) + 1e-6f);
    }
    __syncthreads();

    float xn = x * s_inv * w[i];
    xs[i] = xn;
    __syncthreads();
    float other = (i < 64) ? -xs[i + 64] : xs[i - 64];
    int p = pos_ids[s];
    float c = cosT[(size_t)p * HD + i];
    float sn = sinT[(size_t)p * HD + i];
    float r = xn * c + other * sn;
    bf16 hh = __float2bfloat16(r);
    dh[o] = hh;
    dl[o] = __float2bfloat16(r - __bfloat162float(hh));
}

// =============================================================================
// HMMA flash attention (split-bf16, causal, GQA 4:1)
// grid=(16 q-blocks, 32 heads), 256 threads (8 warps, all-M split 16 rows each)
// BM=128, BN=64, d=128.  P stays in registers (S C-frag -> PV A-frag).
// =============================================================================
#define AT_SMEM 196608

__global__ __launch_bounds__(256) void attn_hmma(
    const bf16* __restrict__ Qh, const bf16* __restrict__ Ql,
    const bf16* __restrict__ Kh, const bf16* __restrict__ Kl,
    const bf16* __restrict__ Vh, const bf16* __restrict__ Vl,
    bf16* __restrict__ Oh, bf16* __restrict__ Ol)
{
    extern __shared__ char smc[];
    uint32_t sb = smem_u32(smc);
    const uint32_t QHo = 0, QLo = 32768, STG0 = 65536, STGSZ = 65536;
    // stage layout: KH +0 (16KB, 2 chunks of 8KB), KL +16384, VH +32768, VL +49152

    int h = blockIdx.y, qb = blockIdx.x;
    int kvh = h >> 2;
    int qbase = qb * 128;
    int tid = threadIdx.x, wid = tid >> 5, lane = tid & 31;
    int warpM = wid * 16;

    // Q loads (bundled into first commit group)
    const bf16* qhs = Qh + ((size_t)h * S_LEN + qbase) * HD;
    const bf16* qls = Ql + ((size_t)h * S_LEN + qbase) * HD;
    #pragma unroll
    for (int i = 0; i < 8; i++) {
        int idx = tid + i * 256;               // 0..2047
        int c = idx >> 10, rem = idx & 1023;
        int row = rem >> 3, c8 = rem & 7;
        uint32_t off = (uint32_t)c * 16384u + SW128((uint32_t)(row * 128 + c8 * 16));
        size_t g = (size_t)row * HD + c * 64 + c8 * 8;
        cpasync16(sb + QHo + off, qhs + g);
        cpasync16(sb + QLo + off, qls + g);
    }

    auto load_kv = [&](int st, int kt) {
        uint32_t sa = sb + STG0 + (uint32_t)st * STGSZ;
        int n0 = kt * 64;
        const bf16* khs = Kh + ((size_t)kvh * S_LEN + n0) * HD;
        const bf16* kls = Kl + ((size_t)kvh * S_LEN + n0) * HD;
        #pragma unroll
        for (int i = 0; i < 4; i++) {
            int idx = tid + i * 256;           // 0..1023
            int c = idx >> 9, row = (idx >> 3) & 63, c8 = idx & 7;
            uint32_t off = (uint32_t)c * 8192u + SW128((uint32_t)(row * 128 + c8 * 16));
            size_t g = (size_t)row * HD + c * 64 + c8 * 8;
            cpasync16(sa + off, khs + g);
            cpasync16(sa + 16384u + off, kls + g);
        }
        const bf16* vhs = Vh + (size_t)kvh * HD * S_LEN + n0;
        const bf16* vls = Vl + (size_t)kvh * HD * S_LEN + n0;
        #pragma unroll
        for (int i = 0; i < 4; i++) {
            int idx = tid + i * 256;
            int row = idx >> 3, c8 = idx & 7;
            uint32_t off = SW128((uint32_t)(row * 128 + c8 * 16));
            size_t g = (size_t)row * S_LEN + c8 * 8;
            cpasync16(sa + 32768u + off, vhs + g);
            cpasync16(sa + 49152u + off, vls + g);
        }
        asm volatile("cp.async.commit_group;" ::: "memory");
    };

    load_kv(0, 0);

    float acc_o[16][4];
    #pragma unroll
    for (int n = 0; n < 16; n++)
        #pragma unroll
        for (int c = 0; c < 4; c++) acc_o[n][c] = 0.f;
    float m0 = -1e30f, m1 = -1e30f, l0 = 0.f, l1 = 0.f;

    int nkt = 2 * (qb + 1);
    const float scale = 0.08838834764831845f;
    uint32_t lrow = lane & 15, lcsel = (lane >> 4) * 16;
    int rowg0 = qbase + warpM + (lane >> 2);

    for (int kt = 0; kt < nkt; kt++) {
        if (kt + 1 < nkt) {
            load_kv((kt + 1) & 1, kt + 1);
            asm volatile("cp.async.wait_group 1;" ::: "memory");
        } else {
            asm volatile("cp.async.wait_group 0;" ::: "memory");
        }
        __syncthreads();
        uint32_t sa = sb + STG0 + (uint32_t)(kt & 1) * STGSZ;
        int n0 = kt * 64;

        // ---- S = Q K^T (3-term split)
        float acc_s[8][4];
        #pragma unroll
        for (int n = 0; n < 8; n++)
            #pragma unroll
            for (int c = 0; c < 4; c++) acc_s[n][c] = 0.f;

        #pragma unroll
        for (int c = 0; c < 2; c++) {
            #pragma unroll
            for (int kk = 0; kk < 4; kk++) {
                uint32_t aoff = (uint32_t)c * 16384u +
                    SW128((uint32_t)((warpM + lrow) * 128) + kk * 32 + lcsel);
                uint32_t aH[4], aL[4];
                LDSM4(aH[0], aH[1], aH[2], aH[3], sb + QHo + aoff);
                LDSM4(aL[0], aL[1], aL[2], aL[3], sb + QLo + aoff);
                #pragma unroll
                for (int kg = 0; kg < 4; kg++) {
                    uint32_t boff = (uint32_t)c * 8192u +
                        SW128((uint32_t)((kg * 16 + lrow) * 128) + kk * 32 + lcsel);
                    uint32_t bH[4], bL[4];
                    LDSM4(bH[0], bH[1], bH[2], bH[3], sa + boff);
                    LDSM4(bL[0], bL[1], bL[2], bL[3], sa + 16384u + boff);
                    #pragma unroll
                    for (int hh = 0; hh < 2; hh++) {
                        int nt = kg * 2 + hh;
                        MMA16816(acc_s[nt], aH[0], aH[1], aH[2], aH[3], bH[hh], bH[hh + 2]);
                        MMA16816(acc_s[nt], aH[0], aH[1], aH[2], aH[3], bL[hh], bL[hh + 2]);
                        MMA16816(acc_s[nt], aL[0], aL[1], aL[2], aL[3], bH[hh], bH[hh + 2]);
                    }
                }
            }
        }

        // ---- scale + causal mask
        bool anymask = (n0 + 64 > qbase + warpM);
        #pragma unroll
        for (int nt = 0; nt < 8; nt++) {
            #pragma unroll
            for (int c = 0; c < 4; c++) acc_s[nt][c] *= scale;
        }
        if (anymask) {
            #pragma unroll
            for (int nt = 0; nt < 8; nt++) {
                int colb = n0 + nt * 8 + (lane & 3) * 2;
                if (colb > rowg0)         acc_s[nt][0] = -1e30f;
                if (colb + 1 > rowg0)     acc_s[nt][1] = -1e30f;
                if (colb > rowg0 + 8)     acc_s[nt][2] = -1e30f;
                if (colb + 1 > rowg0 + 8) acc_s[nt][3] = -1e30f;
            }
        }

        // ---- online softmax (row stats within warp: shfl 1,2)
        float mx0 = -1e30f, mx1 = -1e30f;
        #pragma unroll
        for (int nt = 0; nt < 8; nt++) {
            mx0 = fmaxf(mx0, fmaxf(acc_s[nt][0], acc_s[nt][1]));
            mx1 = fmaxf(mx1, fmaxf(acc_s[nt][2], acc_s[nt][3]));
        }
        mx0 = fmaxf(mx0, __shfl_xor_sync(0xffffffffu, mx0, 1));
        mx0 = fmaxf(mx0, __shfl_xor_sync(0xffffffffu, mx0, 2));
        mx1 = fmaxf(mx1, __shfl_xor_sync(0xffffffffu, mx1, 1));
        mx1 = fmaxf(mx1, __shfl_xor_sync(0xffffffffu, mx1, 2));
        float mn0 = fmaxf(m0, mx0), mn1 = fmaxf(m1, mx1);
        float al0 = __expf(m0 - mn0), al1 = __expf(m1 - mn1);

        float s0 = 0.f, s1 = 0.f;
        #pragma unroll
        for (int nt = 0; nt < 8; nt++) {
            acc_s[nt][0] = __expf(acc_s[nt][0] - mn0);
            acc_s[nt][1] = __expf(acc_s[nt][1] - mn0);
            acc_s[nt][2] = __expf(acc_s[nt][2] - mn1);
            acc_s[nt][3] = __expf(acc_s[nt][3] - mn1);
            s0 += acc_s[nt][0] + acc_s[nt][1];
            s1 += acc_s[nt][2] + acc_s[nt][3];
        }
        s0 += __shfl_xor_sync(0xffffffffu, s0, 1);
        s0 += __shfl_xor_sync(0xffffffffu, s0, 2);
        s1 += __shfl_xor_sync(0xffffffffu, s1, 1);
        s1 += __shfl_xor_sync(0xffffffffu, s1, 2);
        l0 = l0 * al0 + s0; m0 = mn0;
        l1 = l1 * al1 + s1; m1 = mn1;

        // ---- pack P into PV A-fragments (registers only)
        uint32_t paH[4][4], paL[4][4];
        #pragma unroll
        for (int k2 = 0; k2 < 4; k2++) {
            int a = 2 * k2, b = 2 * k2 + 1;
            psplit(acc_s[a][0], acc_s[a][1], paH[k2][0], paL[k2][0]);
            psplit(acc_s[a][2], acc_s[a][3], paH[k2][1], paL[k2][1]);
            psplit(acc_s[b][0], acc_s[b][1], paH[k2][2], paL[k2][2]);
            psplit(acc_s[b][2], acc_s[b][3], paH[k2][3], paL[k2][3]);
        }

        // ---- rescale O
        #pragma unroll
        for (int nt = 0; nt < 16; nt++) {
            acc_o[nt][0] *= al0; acc_o[nt][1] *= al0;
            acc_o[nt][2] *= al1; acc_o[nt][3] *= al1;
        }

        // ---- O += P V (3-term split)
        #pragma unroll
        for (int k2 = 0; k2 < 4; k2++) {
            #pragma unroll
            for (int dg = 0; dg < 8; dg++) {
                uint32_t boff = SW128((uint32_t)((dg * 16 + lrow) * 128) + k2 * 32 + lcsel);
                uint32_t bH[4], bL[4];
                LDSM4(bH[0], bH[1], bH[2], bH[3], sa + 32768u + boff);
                LDSM4(bL[0], bL[1], bL[2], bL[3], sa + 49152u + boff);
                #pragma unroll
                for (int hh = 0; hh < 2; hh++) {
                    int nt = dg * 2 + hh;
                    MMA16816(acc_o[nt], paH[k2][0], paH[k2][1], paH[k2][2], paH[k2][3],
                             bH[hh], bH[hh + 2]);
                    MMA16816(acc_o[nt], paH[k2][0], paH[k2][1], paH[k2][2], paH[k2][3],
                             bL[hh], bL[hh + 2]);
                    MMA16816(acc_o[nt], paL[k2][0], paL[k2][1], paL[k2][2], paL[k2][3],
                             bH[hh], bH[hh + 2]);
                }
            }
        }
        __syncthreads();
    }

    // ---- epilogue: write bf16 hi/lo directly
    float inv0 = 1.0f / l0, inv1 = 1.0f / l1;
    #pragma unroll
    for (int nt = 0; nt < 16; nt++) {
        int col = h * HD + nt * 8 + (lane & 3) * 2;
        float v0 = acc_o[nt][0] * inv0, v1 = acc_o[nt][1] * inv0;
        float v2 = acc_o[nt][2] * inv1, v3 = acc_o[nt][3] * inv1;
        uint32_t hA, lA, hB, lB;
        psplit(v0, v1, hA, lA);
        psplit(v2, v3, hB, lB);
        size_t o0 = (size_t)rowg0 * HID + col;
        size_t o1 = (size_t)(rowg0 + 8) * HID + col;
        *(uint32_t*)&Oh[o0] = hA; *(uint32_t*)&Ol[o0] = lA;
        *(uint32_t*)&Oh[o1] = hB; *(uint32_t*)&Ol[o1] = lB;
    }
}

// =============================================================================
extern "C" void kernel_launch(void* const* d_in, const int* in_sizes, int n_in,
                              void* d_out, int out_size)
{
    const float* hidden = (const float*)d_in[0];
    const int* pos      = (const int*)d_in[1];
    const float* Wq     = (const float*)d_in[2];
    const float* Wk     = (const float*)d_in[3];
    const float* Wv     = (const float*)d_in[4];
    const float* Wo     = (const float*)d_in[5];
    const float* qw     = (const float*)d_in[6];
    const float* kw     = (const float*)d_in[7];
    const float* cosT   = (const float*)d_in[8];
    const float* sinT   = (const float*)d_in[9];
    float* out = (float*)d_out;

    float *qlin, *klin, *vlin;
    cudaGetSymbolAddress((void**)&qlin, g_qlin);
    cudaGetSymbolAddress((void**)&klin, g_klin);
    cudaGetSymbolAddress((void**)&vlin, g_vlin);

    bf16 *hid_hi, *hid_lo, *wq_hi, *wq_lo, *wk_hi, *wk_lo, *wv_hi, *wv_lo;
    bf16 *wo_hi, *wo_lo, *at_hi, *at_lo;
    bf16 *qh, *ql, *kh, *kl, *vth, *vtl;
    cudaGetSymbolAddress((void**)&hid_hi, g_hid_hi);
    cudaGetSymbolAddress((void**)&hid_lo, g_hid_lo);
    cudaGetSymbolAddress((void**)&wq_hi, g_wq_hi);
    cudaGetSymbolAddress((void**)&wq_lo, g_wq_lo);
    cudaGetSymbolAddress((void**)&wk_hi, g_wk_hi);
    cudaGetSymbolAddress((void**)&wk_lo, g_wk_lo);
    cudaGetSymbolAddress((void**)&wv_hi, g_wv_hi);
    cudaGetSymbolAddress((void**)&wv_lo, g_wv_lo);
    cudaGetSymbolAddress((void**)&wo_hi, g_wo_hi);
    cudaGetSymbolAddress((void**)&wo_lo, g_wo_lo);
    cudaGetSymbolAddress((void**)&at_hi, g_attn_hi);
    cudaGetSymbolAddress((void**)&at_lo, g_attn_lo);
    cudaGetSymbolAddress((void**)&qh, g_qh);
    cudaGetSymbolAddress((void**)&ql, g_ql);
    cudaGetSymbolAddress((void**)&kh, g_kh);
    cudaGetSymbolAddress((void**)&kl, g_kl);
    cudaGetSymbolAddress((void**)&vth, g_vth);
    cudaGetSymbolAddress((void**)&vtl, g_vtl);

    cudaFuncSetAttribute(hmma_gemm, cudaFuncAttributeMaxDynamicSharedMemorySize,
                         GEMM_SMEM_BYTES);
    cudaFuncSetAttribute(attn_hmma, cudaFuncAttributeMaxDynamicSharedMemorySize,
                         AT_SMEM);

    // split conversions
    {
        int n4;
        n4 = S_LEN * HID / 4;
        cvt_hilo<<<(n4 + 255) / 256, 256>>>((const float4*)hidden,
            (__nv_bfloat162*)hid_hi, (__nv_bfloat162*)hid_lo, n4);
        n4 = HID * HID / 4;
        cvt_hilo<<<(n4 + 255) / 256, 256>>>((const float4*)Wq,
            (__nv_bfloat162*)wq_hi, (__nv_bfloat162*)wq_lo, n4);
        n4 = (NKV * HD) * HID / 4;
        cvt_hilo<<<(n4 + 255) / 256, 256>>>((const float4*)Wk,
            (__nv_bfloat162*)wk_hi, (__nv_bfloat162*)wk_lo, n4);
        cvt_hilo<<<(n4 + 255) / 256, 256>>>((const float4*)Wv,
            (__nv_bfloat162*)wv_hi, (__nv_bfloat162*)wv_lo, n4);
        n4 = HID * HID / 4;
        cvt_hilo<<<(n4 + 255) / 256, 256>>>((const float4*)Wo,
            (__nv_bfloat162*)wo_hi, (__nv_bfloat162*)wo_lo, n4);
    }

    // projections (HMMA)
    hmma_gemm<<<dim3(HID / 128, S_LEN / 128), 256, GEMM_SMEM_BYTES>>>(
        hid_hi, hid_lo, wq_hi, wq_lo, qlin, S_LEN, HID, HID);
    hmma_gemm<<<dim3((NKV * HD) / 128, S_LEN / 128), 256, GEMM_SMEM_BYTES>>>(
        hid_hi, hid_lo, wk_hi, wk_lo, klin, S_LEN, NKV * HD, HID);
    hmma_gemm<<<dim3((NKV * HD) / 128, S_LEN / 128), 256, GEMM_SMEM_BYTES>>>(
        hid_hi, hid_lo, wv_hi, wv_lo, vlin, S_LEN, NKV * HD, HID);

    // RMSNorm + RoPE -> bf16 hi/lo ; V transpose+split
    qk_norm_rope<<<dim3(S_LEN, NH + NKV), 128>>>(qlin, klin, qw, kw, pos, cosT, sinT,
                                                 qh, ql, kh, kl);
    vt_cvt<<<dim3(S_LEN / 32, (NKV * HD) / 32), dim3(32, 8)>>>(vlin, vth, vtl);

    // HMMA flash attention -> bf16 hi/lo
    attn_hmma<<<dim3(S_LEN / 128, NH), 256, AT_SMEM>>>(qh, ql, kh, kl, vth, vtl,
                                                       at_hi, at_lo);

    // output projection (HMMA)
    hmma_gemm<<<dim3(HID / 128, S_LEN / 128), 256, GEMM_SMEM_BYTES>>>(
        at_hi, at_lo, wo_hi, wo_lo, out, S_LEN, HID, HID);
}